// round 8
// baseline (speedup 1.0000x reference)
#include <cuda_runtime.h>
#include <math.h>

// VMC walker simulation:
//   65536 walkers, 128 warmup + 384 measured Metropolis steps.
//   Streams noise[512][65536] and unif[512][65536] once (256 MiB) -> HBM bound.
//
// Output layout (14 float32), inferred from R3 failure pattern — the complex
// tuple (Es, Ds[3], EDs[3]) is split into real-parts-then-imag-parts:
//   [0]      Es.re
//   [1..3]   Ds.re  = [0, mean(a^2), 2*th1*mean(a)]
//   [4..6]   EDs.re = [mean(e.im*r), mean(e.re*a^2), 2*th1*mean(e.re*a)]
//   [7]      Es.im
//   [8..10]  Ds.im  = [mean(r), 0, 0]
//   [11..13] EDs.im = [-mean(e.re*r), mean(e.im*a^2), 2*th1*mean(e.im*a)]

#define NUM_WALKERS 65536
#define NUM_WARMUP  128
#define NUM_STEPS   384
#define TOTAL_STEPS (NUM_WARMUP + NUM_STEPS)
#define NBLOCKS     128
#define NTHREADS    512
#define NACC        11

// Deterministic per-block partials (no atomics). Scratch via __device__ global
// per harness allocation rules.
__device__ double g_partial[NBLOCKS][NACC];

__global__ __launch_bounds__(NTHREADS, 1)
void vmc_kernel(const float* __restrict__ theta,
                const float* __restrict__ r0,
                const float* __restrict__ s_dev_p,
                const float* __restrict__ noise,
                const float* __restrict__ unif)
{
    const int w = blockIdx.x * NTHREADS + threadIdx.x;   // walker id, 0..65535
    const float th0 = theta[0], th1 = theta[1], th2 = theta[2];
    const float sdev = s_dev_p[0];
    float r = r0[w];

    const float* np = noise + w;
    const float* up = unif + w;

    // ---- warmup: Metropolis only ----
    #pragma unroll 4
    for (int t = 0; t < NUM_WARMUP; ++t) {
        float n = np[(size_t)t * NUM_WALKERS];
        float u = up[(size_t)t * NUM_WALKERS];
        float rp = fmaf(sdev, n, r);
        float a0 = r - th2, ap = rp - th2;
        float logratio = -2.0f * th1 * (ap * ap - a0 * a0);
        if (logf(u) < logratio) r = rp;
    }

    // e = -(t/psi(r)) * (psi(r-1) + psi(r+1))
    //   = -[cos(th0)*(A+B) + i*sin(th0)*(B-A)],  T = 1
    // with a = r - th2, A = exp(th1*(2a-1)), B = exp(-th1*(2a+1)).
    const float cos0 = cosf(th0);
    const float sin0 = sinf(th0);

    float s_er = 0.f, s_ei = 0.f;                 // sum e
    float s_r  = 0.f, s_a  = 0.f, s_a2 = 0.f;     // sum r, a, a^2
    float s_er_r = 0.f, s_ei_r = 0.f;             // sum e * r
    float s_er_a = 0.f, s_ei_a = 0.f;             // sum e * a
    float s_er_a2 = 0.f, s_ei_a2 = 0.f;           // sum e * a^2

    // ---- measurement ----
    #pragma unroll 4
    for (int t = NUM_WARMUP; t < TOTAL_STEPS; ++t) {
        float n = np[(size_t)t * NUM_WALKERS];
        float u = up[(size_t)t * NUM_WALKERS];
        float rp = fmaf(sdev, n, r);
        float a0 = r - th2, ap = rp - th2;
        float logratio = -2.0f * th1 * (ap * ap - a0 * a0);
        if (logf(u) < logratio) r = rp;

        float a  = r - th2;
        float x  = 2.0f * th1 * a;
        float A  = expf(x - th1);
        float B  = expf(-x - th1);
        float e_re = -cos0 * (A + B);
        float e_im = -sin0 * (B - A);
        float a2 = a * a;

        s_er += e_re;  s_ei += e_im;
        s_r  += r;     s_a  += a;    s_a2 += a2;
        s_er_r  = fmaf(e_re, r,  s_er_r);
        s_ei_r  = fmaf(e_im, r,  s_ei_r);
        s_er_a  = fmaf(e_re, a,  s_er_a);
        s_ei_a  = fmaf(e_im, a,  s_ei_a);
        s_er_a2 = fmaf(e_re, a2, s_er_a2);
        s_ei_a2 = fmaf(e_im, a2, s_ei_a2);
    }

    // ---- block reduction (deterministic) ----
    float v[NACC] = { s_er, s_ei, s_r, s_a, s_a2,
                      s_er_r, s_ei_r, s_er_a, s_ei_a, s_er_a2, s_ei_a2 };
    const int lane = threadIdx.x & 31;
    const int warp = threadIdx.x >> 5;

    #pragma unroll
    for (int k = 0; k < NACC; ++k) {
        #pragma unroll
        for (int o = 16; o > 0; o >>= 1)
            v[k] += __shfl_down_sync(0xffffffffu, v[k], o);
    }

    __shared__ float red[NTHREADS / 32][NACC];
    if (lane == 0) {
        #pragma unroll
        for (int k = 0; k < NACC; ++k) red[warp][k] = v[k];
    }
    __syncthreads();

    if (threadIdx.x < NACC) {
        double s = 0.0;
        #pragma unroll
        for (int i = 0; i < NTHREADS / 32; ++i)
            s += (double)red[i][threadIdx.x];
        g_partial[blockIdx.x][threadIdx.x] = s;
    }
}

__global__ void vmc_finalize(const float* __restrict__ theta,
                             float* __restrict__ out)
{
    __shared__ double S[NACC];
    if (threadIdx.x < NACC) {
        double s = 0.0;
        for (int b = 0; b < NBLOCKS; ++b) s += g_partial[b][threadIdx.x];
        S[threadIdx.x] = s;
    }
    __syncthreads();
    if (threadIdx.x == 0) {
        const double scale = 1.0 / ((double)NUM_WALKERS * (double)NUM_STEPS);
        const double th1 = (double)theta[1];
        double er   = S[0]  * scale;   // mean e.re
        double ei   = S[1]  * scale;   // mean e.im
        double mr   = S[2]  * scale;   // mean r
        double ma   = S[3]  * scale;   // mean a
        double ma2  = S[4]  * scale;   // mean a^2
        double err_ = S[5]  * scale;   // mean e.re * r
        double eir  = S[6]  * scale;   // mean e.im * r
        double era  = S[7]  * scale;   // mean e.re * a
        double eia  = S[8]  * scale;   // mean e.im * a
        double era2 = S[9]  * scale;   // mean e.re * a^2
        double eia2 = S[10] * scale;   // mean e.im * a^2

        // ---- real parts ----
        // Es.re
        out[0]  = (float)er;
        // Ds.re: [ (i*mr).re = 0, ma2, 2*th1*ma ]
        out[1]  = 0.0f;
        out[2]  = (float)ma2;
        out[3]  = (float)(2.0 * th1 * ma);
        // EDs.re: EDs[0] = mean(e*conj(i r)) = mean(e.im*r) - i*mean(e.re*r)
        out[4]  = (float)eir;
        out[5]  = (float)era2;
        out[6]  = (float)(2.0 * th1 * era);

        // ---- imag parts ----
        // Es.im
        out[7]  = (float)ei;
        // Ds.im: [ mr, 0, 0 ]
        out[8]  = (float)mr;
        out[9]  = 0.0f;
        out[10] = 0.0f;
        // EDs.im
        out[11] = (float)(-err_);
        out[12] = (float)eia2;
        out[13] = (float)(2.0 * th1 * eia);
    }
}

extern "C" void kernel_launch(void* const* d_in, const int* in_sizes, int n_in,
                              void* d_out, int out_size)
{
    // Identify inputs by size (robust to ordering):
    //   theta: 3, r0: 65536, s_dev: 1, noise/unif: 512*65536 (in dict order).
    const float* theta = nullptr;
    const float* r0    = nullptr;
    const float* sdev  = nullptr;
    const float* noise = nullptr;
    const float* unif  = nullptr;
    const long long big = (long long)TOTAL_STEPS * NUM_WALKERS;
    for (int i = 0; i < n_in; ++i) {
        long long sz = in_sizes[i];
        if (sz == 3)                { theta = (const float*)d_in[i]; }
        else if (sz == 1)           { sdev  = (const float*)d_in[i]; }
        else if (sz == NUM_WALKERS) { r0    = (const float*)d_in[i]; }
        else if (sz == big) {
            if (!noise) noise = (const float*)d_in[i];
            else        unif  = (const float*)d_in[i];
        }
    }

    vmc_kernel<<<NBLOCKS, NTHREADS>>>(theta, r0, sdev, noise, unif);
    vmc_finalize<<<1, 32>>>(theta, (float*)d_out);
}